// round 11
// baseline (speedup 1.0000x reference)
#include <cuda_runtime.h>
#include <cuda_bf16.h>
#include <math.h>

#define EPC        16                 // elements per CTA (fast path)
#define NROWS      22                 // target + context + 20 negatives
#define ROW_BYTES  512                // 128 fp32
#define SLOT_BYTES (NROWS * ROW_BYTES)
#define DEPTH      3                  // pipeline stages (fits in smem w/o losing CTAs)
#define MAX_BLOCKS 8192

__device__ float        g_partial[MAX_BLOCKS];
__device__ unsigned int g_count;      // atomicInc wraps to 0 each run -> deterministic

__device__ __forceinline__ float log_sigmoid(float x) {
    return fminf(x, 0.0f) - log1pf(__expf(-fabsf(x)));
}

__device__ __forceinline__ unsigned smem_u32(const void* p) {
    return (unsigned)__cvta_generic_to_shared(p);
}

__device__ __forceinline__ void mbar_init(unsigned mbar, unsigned count) {
    asm volatile("mbarrier.init.shared.b64 [%0], %1;" :: "r"(mbar), "r"(count) : "memory");
}
__device__ __forceinline__ void mbar_expect_tx(unsigned mbar, unsigned bytes) {
    asm volatile("mbarrier.arrive.expect_tx.shared.b64 _, [%0], %1;"
                 :: "r"(mbar), "r"(bytes) : "memory");
}
__device__ __forceinline__ void mbar_wait(unsigned mbar, unsigned parity) {
    asm volatile(
        "{\n\t.reg .pred P;\n\t"
        "WAIT_%=:\n\t"
        "mbarrier.try_wait.parity.acquire.cta.shared::cta.b64 P, [%0], %1, 0x989680;\n\t"
        "@!P bra WAIT_%=;\n\t}"
        :: "r"(mbar), "r"(parity) : "memory");
}
__device__ __forceinline__ void bulk_cp(unsigned dst_smem, const void* src, unsigned bytes,
                                        unsigned mbar) {
    asm volatile(
        "cp.async.bulk.shared::cta.global.mbarrier::complete_tx::bytes [%0], [%1], %2, [%3];"
        :: "r"(dst_smem), "l"(src), "r"(bytes), "r"(mbar) : "memory");
}

// Fast path: 3-deep async bulk-copy gather pipeline, 16 elems/CTA, grid 1024.
// smem ~35.5 KB -> ~6.4 CTAs/SM, matching the grid limit (1024/148=6.9), so
// depth 3 costs no residency vs R8 while adding a 3rd in-flight stream per CTA.
__global__ void __launch_bounds__(128, 6)
skipgram_bulk(const int* __restrict__ target,
              const int* __restrict__ context,
              const int* __restrict__ neg,
              const char* __restrict__ emb_bytes,
              float* __restrict__ out,
              int B, int nblocks)
{
    __shared__ __align__(128) char buf[DEPTH][SLOT_BYTES];   // 33.75 KB
    __shared__ int   s_idx[EPC][NROWS];
    __shared__ unsigned long long s_mbar[DEPTH];
    __shared__ float s_pos[DEPTH][4], s_neg[DEPTH][4];
    __shared__ float s_red[4];
    __shared__ int   s_last;

    const int tid  = threadIdx.x;
    const int lane = tid & 31;
    const int wid  = tid >> 5;
    const int b0   = blockIdx.x * EPC;

    // Stage all indices for this CTA's 16 elements.
    for (int i = tid; i < EPC * NROWS; i += 128) {
        int e = i / NROWS, r = i % NROWS;
        int b = b0 + e;
        int idx = (r == 0) ? target[b] : (r == 1) ? context[b] : neg[b * 20 + (r - 2)];
        s_idx[e][r] = idx;
    }
    if (tid < DEPTH) mbar_init(smem_u32(&s_mbar[tid]), 1);
    asm volatile("fence.proxy.async.shared::cta;" ::: "memory");
    __syncthreads();

    // Issue element e's 22 row-copies into slot e%DEPTH.
    #define ISSUE(e_)                                                          \
        do {                                                                   \
            int slot_ = (e_) % DEPTH;                                          \
            unsigned mb_ = smem_u32(&s_mbar[slot_]);                           \
            if (lane == 0) mbar_expect_tx(mb_, SLOT_BYTES);                    \
            __syncwarp();                                                      \
            if (lane < NROWS) {                                                \
                long long idx_ = s_idx[e_][lane];                              \
                bulk_cp(smem_u32(&buf[slot_][lane * ROW_BYTES]),               \
                        emb_bytes + idx_ * ROW_BYTES, ROW_BYTES, mb_);         \
            }                                                                  \
        } while (0)

    if (wid == 0) { ISSUE(0); ISSUE(1); ISSUE(2); }

    float acc = 0.0f;   // meaningful on thread 0 only

    #pragma unroll 1
    for (int e = 0; e < EPC; ++e) {
        const int slot  = e % DEPTH;
        const int phase = (e / DEPTH) & 1;        // flips each slot reuse
        mbar_wait(smem_u32(&s_mbar[slot]), phase);

        const float* rows = (const float*)buf[slot];
        float v = rows[0 * 128 + tid];
        float u = rows[1 * 128 + tid];
        float s = 0.0f;
        #pragma unroll
        for (int k = 0; k < 20; ++k)
            s += rows[(2 + k) * 128 + tid];

        float pos_p = u * v;
        float neg_p = s * v;
        #pragma unroll
        for (int off = 16; off > 0; off >>= 1) {
            pos_p += __shfl_down_sync(0xffffffffu, pos_p, off);
            neg_p += __shfl_down_sync(0xffffffffu, neg_p, off);
        }
        if (lane == 0) { s_pos[slot][wid] = pos_p; s_neg[slot][wid] = neg_p; }
        __syncthreads();   // all warps done reading slot; partials visible

        if (tid == 0) {
            float duv = s_pos[slot][0] + s_pos[slot][1] + s_pos[slot][2] + s_pos[slot][3];
            float dsv = s_neg[slot][0] + s_neg[slot][1] + s_neg[slot][2] + s_neg[slot][3];
            acc += log_sigmoid(duv) + log_sigmoid(-dsv);
        }
        if (wid == 0 && e + DEPTH < EPC) ISSUE(e + DEPTH);   // refill drained slot
    }

    if (tid == 0) {
        g_partial[blockIdx.x] = acc;
        __threadfence();
        unsigned prev = atomicInc(&g_count, (unsigned)(nblocks - 1)); // wraps to 0
        s_last = (prev == (unsigned)(nblocks - 1)) ? 1 : 0;
    }
    __syncthreads();

    if (s_last) {
        __threadfence();
        float a = 0.0f;
        for (int i = tid; i < nblocks; i += 128)
            a += g_partial[i];
        #pragma unroll
        for (int off = 16; off > 0; off >>= 1)
            a += __shfl_down_sync(0xffffffffu, a, off);
        if (lane == 0) s_red[wid] = a;
        __syncthreads();
        if (tid == 0)
            out[0] = -(s_red[0] + s_red[1] + s_red[2] + s_red[3]) / (float)B;
    }
}

// Generic fallback for K != 20 or B % EPC != 0 (proven structure).
#define ELEMS_PER_CTA 8
__global__ void __launch_bounds__(128, 16)
skipgram_fallback(const int* __restrict__ target,
                  const int* __restrict__ context,
                  const int* __restrict__ neg,
                  const float* __restrict__ emb,
                  float* __restrict__ out,
                  int B, int K, int nblocks)
{
    const int d    = threadIdx.x;
    const int lane = d & 31;
    const int wid  = d >> 5;

    __shared__ float s_red[8];
    __shared__ int   s_last;

    float acc = 0.0f;
    const int b0 = blockIdx.x * ELEMS_PER_CTA;

    #pragma unroll 1
    for (int e = 0; e < ELEMS_PER_CTA; ++e) {
        const int b = b0 + e;
        if (b < B) {
            const int t = target[b];
            const int c = context[b];
            int my_neg = (lane < K && lane < 32) ? neg[b * K + lane] : 0;

            const float v = __ldg(&emb[(long long)t * 128 + d]);
            const float u = __ldg(&emb[(long long)c * 128 + d]);

            float s = 0.0f;
            for (int k = 0; k < K; ++k) {
                int idx = (k < 32) ? __shfl_sync(0xffffffffu, my_neg, k)
                                   : neg[b * K + k];
                s += __ldg(&emb[(long long)idx * 128 + d]);
            }

            float pos_p = u * v;
            float neg_p = s * v;
            #pragma unroll
            for (int off = 16; off > 0; off >>= 1) {
                pos_p += __shfl_down_sync(0xffffffffu, pos_p, off);
                neg_p += __shfl_down_sync(0xffffffffu, neg_p, off);
            }
            if (lane == 0) {
                s_red[wid]     = pos_p;
                s_red[wid + 4] = neg_p;
            }
        }
        __syncthreads();
        if (d == 0 && b < B) {
            float duv = s_red[0] + s_red[1] + s_red[2] + s_red[3];
            float dsv = s_red[4] + s_red[5] + s_red[6] + s_red[7];
            acc += log_sigmoid(duv) + log_sigmoid(-dsv);
        }
        __syncthreads();
    }

    if (d == 0) {
        g_partial[blockIdx.x] = acc;
        __threadfence();
        unsigned prev = atomicInc(&g_count, (unsigned)(nblocks - 1));
        s_last = (prev == (unsigned)(nblocks - 1)) ? 1 : 0;
    }
    __syncthreads();

    if (s_last) {
        __threadfence();
        float a = 0.0f;
        for (int i = d; i < nblocks; i += 128)
            a += g_partial[i];
        #pragma unroll
        for (int off = 16; off > 0; off >>= 1)
            a += __shfl_down_sync(0xffffffffu, a, off);
        if (lane == 0) s_red[wid] = a;
        __syncthreads();
        if (d == 0)
            out[0] = -(s_red[0] + s_red[1] + s_red[2] + s_red[3]) / (float)B;
    }
}

extern "C" void kernel_launch(void* const* d_in, const int* in_sizes, int n_in,
                              void* d_out, int out_size)
{
    const int*   target  = (const int*)d_in[0];
    const int*   context = (const int*)d_in[1];
    const int*   neg     = (const int*)d_in[2];
    const float* emb     = (const float*)d_in[3];
    float*       out     = (float*)d_out;

    const int B = in_sizes[0];
    const int K = in_sizes[2] / B;

    if (K == 20 && (B % EPC) == 0 && (B / EPC) <= MAX_BLOCKS) {
        const int nblocks = B / EPC;   // 1024
        skipgram_bulk<<<nblocks, 128>>>(target, context, neg,
                                        (const char*)emb, out, B, nblocks);
    } else {
        const int nblocks = (B + ELEMS_PER_CTA - 1) / ELEMS_PER_CTA;
        skipgram_fallback<<<nblocks, 128>>>(target, context, neg, emb, out, B, K, nblocks);
    }
}

// round 12
// speedup vs baseline: 1.4321x; 1.4321x over previous
#include <cuda_runtime.h>
#include <cuda_bf16.h>
#include <math.h>

#define EPC        16                 // elements per CTA (fast path)
#define NROWS      22                 // target + context + 20 negatives
#define ROW_BYTES  512                // 128 fp32
#define SLOT_BYTES (NROWS * ROW_BYTES)
#define DEPTH      2                  // pipeline stages (R8-proven optimum)
#define MAX_BLOCKS 8192

__device__ float        g_partial[MAX_BLOCKS];
__device__ unsigned int g_count;      // atomicInc wraps to 0 each run -> deterministic

__device__ __forceinline__ float log_sigmoid(float x) {
    return fminf(x, 0.0f) - log1pf(__expf(-fabsf(x)));
}

__device__ __forceinline__ unsigned smem_u32(const void* p) {
    return (unsigned)__cvta_generic_to_shared(p);
}

__device__ __forceinline__ void mbar_init(unsigned mbar, unsigned count) {
    asm volatile("mbarrier.init.shared.b64 [%0], %1;" :: "r"(mbar), "r"(count) : "memory");
}
__device__ __forceinline__ void mbar_expect_tx(unsigned mbar, unsigned bytes) {
    asm volatile("mbarrier.arrive.expect_tx.shared.b64 _, [%0], %1;"
                 :: "r"(mbar), "r"(bytes) : "memory");
}
__device__ __forceinline__ void mbar_wait(unsigned mbar, unsigned parity) {
    asm volatile(
        "{\n\t.reg .pred P;\n\t"
        "WAIT_%=:\n\t"
        "mbarrier.try_wait.parity.acquire.cta.shared::cta.b64 P, [%0], %1, 0x989680;\n\t"
        "@!P bra WAIT_%=;\n\t}"
        :: "r"(mbar), "r"(parity) : "memory");
}
__device__ __forceinline__ void bulk_cp(unsigned dst_smem, const void* src, unsigned bytes,
                                        unsigned mbar) {
    asm volatile(
        "cp.async.bulk.shared::cta.global.mbarrier::complete_tx::bytes [%0], [%1], %2, [%3];"
        :: "r"(dst_smem), "l"(src), "r"(bytes), "r"(mbar) : "memory");
}

// Packed f32x2 add (Blackwell): one instruction sums both dot partials.
__device__ __forceinline__ unsigned long long addf32x2(unsigned long long a,
                                                       unsigned long long b) {
    unsigned long long o;
    asm("add.rn.f32x2 %0, %1, %2;" : "=l"(o) : "l"(a), "l"(b));
    return o;
}

// Fast path (exact R8 structure): 2-deep async bulk-copy gather pipeline,
// 16 elems/CTA, grid 1024.
__global__ void __launch_bounds__(128, 8)
skipgram_bulk(const int* __restrict__ target,
              const int* __restrict__ context,
              const int* __restrict__ neg,
              const char* __restrict__ emb_bytes,
              float* __restrict__ out,
              int B, int nblocks)
{
    __shared__ __align__(128) char buf[DEPTH][SLOT_BYTES];   // 22.5 KB
    __shared__ int   s_idx[EPC][NROWS];
    __shared__ unsigned long long s_mbar[DEPTH];
    __shared__ float s_pos[DEPTH][4], s_neg[DEPTH][4];
    __shared__ float s_red[4];
    __shared__ int   s_last;

    const int tid  = threadIdx.x;
    const int lane = tid & 31;
    const int wid  = tid >> 5;
    const int b0   = blockIdx.x * EPC;

    // Stage all indices for this CTA's 16 elements.
    for (int i = tid; i < EPC * NROWS; i += 128) {
        int e = i / NROWS, r = i % NROWS;
        int b = b0 + e;
        int idx = (r == 0) ? target[b] : (r == 1) ? context[b] : neg[b * 20 + (r - 2)];
        s_idx[e][r] = idx;
    }
    if (tid < DEPTH) mbar_init(smem_u32(&s_mbar[tid]), 1);
    asm volatile("fence.proxy.async.shared::cta;" ::: "memory");
    __syncthreads();

    // Issue element e's 22 row-copies into slot e%DEPTH.
    #define ISSUE(e_)                                                          \
        do {                                                                   \
            int slot_ = (e_) & (DEPTH - 1);                                    \
            unsigned mb_ = smem_u32(&s_mbar[slot_]);                           \
            if (lane == 0) mbar_expect_tx(mb_, SLOT_BYTES);                    \
            __syncwarp();                                                      \
            if (lane < NROWS) {                                                \
                long long idx_ = s_idx[e_][lane];                              \
                bulk_cp(smem_u32(&buf[slot_][lane * ROW_BYTES]),               \
                        emb_bytes + idx_ * ROW_BYTES, ROW_BYTES, mb_);         \
            }                                                                  \
        } while (0)

    if (wid == 0) { ISSUE(0); ISSUE(1); }

    float acc = 0.0f;   // meaningful on thread 0 only

    #pragma unroll 1
    for (int e = 0; e < EPC; ++e) {
        const int slot  = e & (DEPTH - 1);
        const int phase = (e >> 1) & 1;           // flips each slot reuse
        mbar_wait(smem_u32(&s_mbar[slot]), phase);

        const float* rows = (const float*)buf[slot];
        float v = rows[0 * 128 + tid];
        float u = rows[1 * 128 + tid];
        float s = 0.0f;
        #pragma unroll
        for (int k = 0; k < 20; ++k)
            s += rows[(2 + k) * 128 + tid];

        // Pack both dot partials -> single shuffle-reduce chain via add.f32x2.
        float2 pp = make_float2(u * v, s * v);
        unsigned long long packed = *(unsigned long long*)&pp;
        #pragma unroll
        for (int off = 16; off > 0; off >>= 1) {
            unsigned long long other = __shfl_down_sync(0xffffffffu, packed, off);
            packed = addf32x2(packed, other);
        }
        if (lane == 0) {
            float2 r = *(float2*)&packed;
            s_pos[slot][wid] = r.x;
            s_neg[slot][wid] = r.y;
        }
        __syncthreads();   // all warps done reading slot; partials visible

        if (tid == 0) {
            float duv = s_pos[slot][0] + s_pos[slot][1] + s_pos[slot][2] + s_pos[slot][3];
            float dsv = s_neg[slot][0] + s_neg[slot][1] + s_neg[slot][2] + s_neg[slot][3];
            acc += log_sigmoid(duv) + log_sigmoid(-dsv);
        }
        if (wid == 0 && e + DEPTH < EPC) ISSUE(e + DEPTH);   // refill drained slot
    }

    if (tid == 0) {
        g_partial[blockIdx.x] = acc;
        __threadfence();
        unsigned prev = atomicInc(&g_count, (unsigned)(nblocks - 1)); // wraps to 0
        s_last = (prev == (unsigned)(nblocks - 1)) ? 1 : 0;
    }
    __syncthreads();

    if (s_last) {
        __threadfence();
        float a = 0.0f;
        for (int i = tid; i < nblocks; i += 128)
            a += g_partial[i];
        #pragma unroll
        for (int off = 16; off > 0; off >>= 1)
            a += __shfl_down_sync(0xffffffffu, a, off);
        if (lane == 0) s_red[wid] = a;
        __syncthreads();
        if (tid == 0)
            out[0] = -(s_red[0] + s_red[1] + s_red[2] + s_red[3]) / (float)B;
    }
}

// Generic fallback for K != 20 or B % EPC != 0 (proven structure).
#define ELEMS_PER_CTA 8
__global__ void __launch_bounds__(128, 16)
skipgram_fallback(const int* __restrict__ target,
                  const int* __restrict__ context,
                  const int* __restrict__ neg,
                  const float* __restrict__ emb,
                  float* __restrict__ out,
                  int B, int K, int nblocks)
{
    const int d    = threadIdx.x;
    const int lane = d & 31;
    const int wid  = d >> 5;

    __shared__ float s_red[8];
    __shared__ int   s_last;

    float acc = 0.0f;
    const int b0 = blockIdx.x * ELEMS_PER_CTA;

    #pragma unroll 1
    for (int e = 0; e < ELEMS_PER_CTA; ++e) {
        const int b = b0 + e;
        if (b < B) {
            const int t = target[b];
            const int c = context[b];
            int my_neg = (lane < K && lane < 32) ? neg[b * K + lane] : 0;

            const float v = __ldg(&emb[(long long)t * 128 + d]);
            const float u = __ldg(&emb[(long long)c * 128 + d]);

            float s = 0.0f;
            for (int k = 0; k < K; ++k) {
                int idx = (k < 32) ? __shfl_sync(0xffffffffu, my_neg, k)
                                   : neg[b * K + k];
                s += __ldg(&emb[(long long)idx * 128 + d]);
            }

            float pos_p = u * v;
            float neg_p = s * v;
            #pragma unroll
            for (int off = 16; off > 0; off >>= 1) {
                pos_p += __shfl_down_sync(0xffffffffu, pos_p, off);
                neg_p += __shfl_down_sync(0xffffffffu, neg_p, off);
            }
            if (lane == 0) {
                s_red[wid]     = pos_p;
                s_red[wid + 4] = neg_p;
            }
        }
        __syncthreads();
        if (d == 0 && b < B) {
            float duv = s_red[0] + s_red[1] + s_red[2] + s_red[3];
            float dsv = s_red[4] + s_red[5] + s_red[6] + s_red[7];
            acc += log_sigmoid(duv) + log_sigmoid(-dsv);
        }
        __syncthreads();
    }

    if (d == 0) {
        g_partial[blockIdx.x] = acc;
        __threadfence();
        unsigned prev = atomicInc(&g_count, (unsigned)(nblocks - 1));
        s_last = (prev == (unsigned)(nblocks - 1)) ? 1 : 0;
    }
    __syncthreads();

    if (s_last) {
        __threadfence();
        float a = 0.0f;
        for (int i = d; i < nblocks; i += 128)
            a += g_partial[i];
        #pragma unroll
        for (int off = 16; off > 0; off >>= 1)
            a += __shfl_down_sync(0xffffffffu, a, off);
        if (lane == 0) s_red[wid] = a;
        __syncthreads();
        if (d == 0)
            out[0] = -(s_red[0] + s_red[1] + s_red[2] + s_red[3]) / (float)B;
    }
}

extern "C" void kernel_launch(void* const* d_in, const int* in_sizes, int n_in,
                              void* d_out, int out_size)
{
    const int*   target  = (const int*)d_in[0];
    const int*   context = (const int*)d_in[1];
    const int*   neg     = (const int*)d_in[2];
    const float* emb     = (const float*)d_in[3];
    float*       out     = (float*)d_out;

    const int B = in_sizes[0];
    const int K = in_sizes[2] / B;

    if (K == 20 && (B % EPC) == 0 && (B / EPC) <= MAX_BLOCKS) {
        const int nblocks = B / EPC;   // 1024
        skipgram_bulk<<<nblocks, 128>>>(target, context, neg,
                                        (const char*)emb, out, B, nblocks);
    } else {
        const int nblocks = (B + ELEMS_PER_CTA - 1) / ELEMS_PER_CTA;
        skipgram_fallback<<<nblocks, 128>>>(target, context, neg, emb, out, B, K, nblocks);
    }
}